// round 14
// baseline (speedup 1.0000x reference)
#include <cuda_runtime.h>
#include <cstdint>

// Identity op: reference output == input X. Pure 128 MiB HBM copy.
//
// R13 experiment: PERSISTENT single-wave kernel. All prior variants used
// one-shot grids (4096 blocks = 7 waves at occ~50%); the composed T_chip
// model charges (n_waves-1)*(T_wave_trans + spread-lift) — potentially
// several us. Here: grid = 592 blocks (148 SMs x 4 CTAs, exactly one
// resident wave), each block grid-strides over ~14 iterations of the
// proven body (4 x 256-bit v8.f32 per thread, loads front-batched).

__device__ __forceinline__ void ldg256(const float* __restrict__ p, float* v) {
    asm volatile(
        "ld.global.nc.v8.f32 {%0,%1,%2,%3,%4,%5,%6,%7}, [%8];"
        : "=f"(v[0]), "=f"(v[1]), "=f"(v[2]), "=f"(v[3]),
          "=f"(v[4]), "=f"(v[5]), "=f"(v[6]), "=f"(v[7])
        : "l"(p));
}

__device__ __forceinline__ void stg256(float* __restrict__ p, const float* v) {
    asm volatile(
        "st.global.v8.f32 [%0], {%1,%2,%3,%4,%5,%6,%7,%8};"
        :: "l"(p),
           "f"(v[0]), "f"(v[1]), "f"(v[2]), "f"(v[3]),
           "f"(v[4]), "f"(v[5]), "f"(v[6]), "f"(v[7])
        : "memory");
}

constexpr int V8PT = 4;        // 4 x 32 B = 128 B per thread per iteration
constexpr int THREADS = 256;
constexpr int PERSIST_BLOCKS = 592;  // 148 SMs x 4 CTAs -> one resident wave

__global__ void __launch_bounds__(THREADS)
copy_v8_persist_kernel(const float* __restrict__ src,
                       float* __restrict__ dst,
                       long long n8) {   // count of float8 chunks
    const long long iter_span = (long long)gridDim.x * (THREADS * V8PT);
    long long base = (long long)blockIdx.x * (THREADS * V8PT) + threadIdx.x;

    for (; base < n8 + (long long)(V8PT - 1) * THREADS; base += iter_span) {
        float v[V8PT][8];
        #pragma unroll
        for (int j = 0; j < V8PT; j++) {
            long long i = base + (long long)j * THREADS;
            if (i < n8) ldg256(src + i * 8, v[j]);
        }
        #pragma unroll
        for (int j = 0; j < V8PT; j++) {
            long long i = base + (long long)j * THREADS;
            if (i < n8) stg256(dst + i * 8, v[j]);
        }
    }
}

// Scalar fallback for arbitrary sizes/alignment.
__global__ void copy_f1_kernel(const float* __restrict__ src,
                               float* __restrict__ dst,
                               long long n) {
    long long i = (long long)blockIdx.x * blockDim.x + threadIdx.x;
    long long stride = (long long)gridDim.x * blockDim.x;
    for (; i < n; i += stride) dst[i] = src[i];
}

extern "C" void kernel_launch(void* const* d_in, const int* in_sizes, int n_in,
                              void* d_out, int out_size) {
    const float* x = (const float*)d_in[0];
    float* out = (float*)d_out;
    long long n = (long long)out_size;   // 33,554,432 floats expected

    if ((n & 7) == 0 && (((uintptr_t)x | (uintptr_t)out) & 31) == 0) {
        long long n8 = n >> 3;
        // Don't launch more blocks than needed for tiny sizes.
        long long per_block_iter = (long long)THREADS * V8PT;  // 1024 float8
        long long need = (n8 + per_block_iter - 1) / per_block_iter;
        int blocks = (need < PERSIST_BLOCKS) ? (int)need : PERSIST_BLOCKS;
        if (blocks < 1) blocks = 1;
        copy_v8_persist_kernel<<<blocks, THREADS>>>(x, out, n8);
        return;
    }
    int blocks = (int)(((n >> 2) + 255) / 256);
    if (blocks < 1) blocks = 1;
    if (blocks > 262144) blocks = 262144;
    copy_f1_kernel<<<blocks, 256>>>(x, out, n);
}

// round 15
// speedup vs baseline: 1.1335x; 1.1335x over previous
#include <cuda_runtime.h>
#include <cstdint>

// Identity op: reference output == input X (the torch module's loop writes
// are dead code; output is exactly the input tensor). Pure 128 MiB HBM copy.
//
// FINAL — converged after 10 benched variants. Mixed read+write DRAM
// ceiling on this part is ~7.1-7.3 TB/s effective; this config measured
// 36.7/36.9/37.6/37.2us kernel across four runs (best wall 44.9us).
// Falsified alternatives: cache operators, L2 eviction priorities, L2
// residency schemes, driver memcpy node, 512-thread blocks, paired
// interleave, predicate-free exact-fit (occupancy-induced L1tex
// contention), persistent single-wave grid (serializes the load stream).
//
// Config: 256-thread blocks, 4 x 256-bit v8.f32 per thread, loads
// front-batched (MLP=4), bounds-predicated (regs ~44 -> occ ~50%, the
// empirically best point for this streaming pattern).

__device__ __forceinline__ void ldg256(const float* __restrict__ p, float* v) {
    asm volatile(
        "ld.global.nc.v8.f32 {%0,%1,%2,%3,%4,%5,%6,%7}, [%8];"
        : "=f"(v[0]), "=f"(v[1]), "=f"(v[2]), "=f"(v[3]),
          "=f"(v[4]), "=f"(v[5]), "=f"(v[6]), "=f"(v[7])
        : "l"(p));
}

__device__ __forceinline__ void stg256(float* __restrict__ p, const float* v) {
    asm volatile(
        "st.global.v8.f32 [%0], {%1,%2,%3,%4,%5,%6,%7,%8};"
        :: "l"(p),
           "f"(v[0]), "f"(v[1]), "f"(v[2]), "f"(v[3]),
           "f"(v[4]), "f"(v[5]), "f"(v[6]), "f"(v[7])
        : "memory");
}

constexpr int V8PT = 4;      // 4 x 32 B = 128 B per thread
constexpr int THREADS = 256;

__global__ void __launch_bounds__(THREADS)
copy_v8_kernel(const float* __restrict__ src,
               float* __restrict__ dst,
               long long n8) {   // count of float8 chunks
    long long base = (long long)blockIdx.x * (THREADS * V8PT) + threadIdx.x;

    float v[V8PT][8];
    // Front-batch all loads: 4 independent 256-bit LDGs in flight per thread.
    #pragma unroll
    for (int j = 0; j < V8PT; j++) {
        long long i = base + (long long)j * THREADS;
        if (i < n8) ldg256(src + i * 8, v[j]);
    }
    #pragma unroll
    for (int j = 0; j < V8PT; j++) {
        long long i = base + (long long)j * THREADS;
        if (i < n8) stg256(dst + i * 8, v[j]);
    }
}

// Scalar fallback for arbitrary sizes/alignment (not expected: n = 2^25,
// buffers 256B-aligned by the allocator).
__global__ void copy_f1_kernel(const float* __restrict__ src,
                               float* __restrict__ dst,
                               long long n) {
    long long i = (long long)blockIdx.x * blockDim.x + threadIdx.x;
    long long stride = (long long)gridDim.x * blockDim.x;
    for (; i < n; i += stride) dst[i] = src[i];
}

extern "C" void kernel_launch(void* const* d_in, const int* in_sizes, int n_in,
                              void* d_out, int out_size) {
    const float* x = (const float*)d_in[0];
    float* out = (float*)d_out;
    long long n = (long long)out_size;   // 33,554,432 floats expected

    if ((n & 7) == 0 && (((uintptr_t)x | (uintptr_t)out) & 31) == 0) {
        long long n8 = n >> 3;
        const long long per_block = (long long)THREADS * V8PT;   // 1024 float8
        long long blocks_ll = (n8 + per_block - 1) / per_block;  // 4096 expected
        if (blocks_ll <= 1048576LL) {
            copy_v8_kernel<<<(int)blocks_ll, THREADS>>>(x, out, n8);
            return;
        }
    }
    int blocks = (int)(((n >> 2) + 255) / 256);
    if (blocks < 1) blocks = 1;
    if (blocks > 262144) blocks = 262144;
    copy_f1_kernel<<<blocks, 256>>>(x, out, n);
}